// round 9
// baseline (speedup 1.0000x reference)
#include <cuda_runtime.h>
#include <cstdint>

#define DEVINL __device__ __forceinline__

// ---------------- problem dims ----------------
#define B_SZ   8
#define S_SZ   4096
#define D_IN   1280
#define D_OUT  1280
#define N_L    4
#define R_L    16
#define J_L    64                 /* N_L * R_L */
#define M_ROWS 32768              /* B_SZ * S_SZ */
#define K_TOT  1344               /* D_IN + J_L  */

// ---------------- tiling ----------------
#define KC      16                /* K per stage */
#define NT_ALL  (K_TOT / KC)      /* 84 */
#define NT_X    (D_IN / KC)       /* 80 */
#define STAGES  3

// Pre-swizzled, tf32-pre-rounded operand tensors.
//   Xt[mtile][ktile][2048]  (mtile = m>>7), Wt[ntile][ktile][2048]
//   At[ktile][1024]  (Acat, 64 rows)
// In-tile layout (m, kk = k&15):
//   fidx(m,kk) = (m>>1)*32 + (((4*(m&1) + (kk>>2)) ^ ((m>>1)&7)) << 2) + (kk&3)
// Halves are self-contained: rows [0,64) -> floats [0,1024), rows [64,128) -> [1024,2048).
__device__ float Xt[(size_t)(M_ROWS / 128) * NT_ALL * 2048];
__device__ float Wt[(size_t)(D_OUT / 128) * NT_ALL * 2048];
__device__ float At[(size_t)NT_X * 1024];

// ---------------- helpers ----------------
DEVINL uint32_t tf32b(float x) {
    uint32_t r;
    asm("cvt.rna.tf32.f32 %0, %1;" : "=r"(r) : "f"(x));
    return r;
}
DEVINL float tf32f(float x) { uint32_t r = tf32b(x); return __uint_as_float(r); }

DEVINL void mma_tf32(float c[4], uint32_t a0, uint32_t a1, uint32_t a2, uint32_t a3,
                     uint32_t b0, uint32_t b1) {
    asm volatile(
        "mma.sync.aligned.m16n8k8.row.col.f32.tf32.tf32.f32 "
        "{%0,%1,%2,%3}, {%4,%5,%6,%7}, {%8,%9}, {%0,%1,%2,%3};"
        : "+f"(c[0]), "+f"(c[1]), "+f"(c[2]), "+f"(c[3])
        : "r"(a0), "r"(a1), "r"(a2), "r"(a3), "r"(b0), "r"(b1));
}
DEVINL void ldsm4(uint32_t r[4], uint32_t addr) {
    asm volatile("ldmatrix.sync.aligned.m8n8.x4.shared.b16 {%0,%1,%2,%3}, [%4];"
                 : "=r"(r[0]), "=r"(r[1]), "=r"(r[2]), "=r"(r[3]) : "r"(addr));
}
DEVINL uint32_t smem_u32(const void* p) {
    uint32_t a;
    asm("{ .reg .u64 t; cvta.to.shared.u64 t, %1; cvt.u32.u64 %0, t; }" : "=r"(a) : "l"(p));
    return a;
}
DEVINL void cp16(uint32_t smem, const void* gptr) {
    asm volatile("cp.async.cg.shared.global [%0], [%1], 16;" :: "r"(smem), "l"(gptr) : "memory");
}
#define CP_COMMIT() asm volatile("cp.async.commit_group;" ::: "memory")
#define CP_WAIT2()  asm volatile("cp.async.wait_group 2;" ::: "memory")

DEVINL uint32_t fidx_sw(int m, int kk) {
    int p = m >> 1, q = m & 1;
    return (uint32_t)(p * 32 + (((4 * q + (kk >> 2)) ^ (p & 7)) << 2) + (kk & 3));
}

// ============================================================================
// Kernel 0a: Xt[mt][kt<80] = swizzled tf32(X)
// ============================================================================
__global__ void __launch_bounds__(128)
convert_x_kernel(const float* __restrict__ X)
{
    const int tid = threadIdx.x;
    const int mt = blockIdx.x, kt = blockIdx.y;
    float* dst = Xt + ((size_t)mt * NT_ALL + kt) * 2048;
    #pragma unroll
    for (int i = 0; i < 4; i++) {
        int idx = tid + i * 128;
        int m = idx >> 2, c = idx & 3;
        float4 v = *(const float4*)(X + (size_t)(mt * 128 + m) * D_IN + kt * KC + c * 4);
        float4 o = { tf32f(v.x), tf32f(v.y), tf32f(v.z), tf32f(v.w) };
        *(float4*)(dst + fidx_sw(m, c * 4)) = o;
    }
}

// ============================================================================
// Kernel 0b: Wt[nt][kt] from W (kt<80) / Bcat gather (kt>=80)
//   Bcat[o][j] = Bw[j>>4][o][j&15]
// ============================================================================
__global__ void __launch_bounds__(128)
convert_w_kernel(const float* __restrict__ W, const float* __restrict__ Bw)
{
    const int tid = threadIdx.x;
    const int nt = blockIdx.x, kt = blockIdx.y;
    float* dst = Wt + ((size_t)nt * NT_ALL + kt) * 2048;
    #pragma unroll
    for (int i = 0; i < 4; i++) {
        int idx = tid + i * 128;
        int m = idx >> 2, c = idx & 3;
        float4 v;
        if (kt < NT_X) {
            v = *(const float4*)(W + (size_t)(nt * 128 + m) * D_IN + kt * KC + c * 4);
        } else {
            v = *(const float4*)(Bw + (size_t)(kt - NT_X) * (D_OUT * R_L)
                                    + (size_t)(nt * 128 + m) * R_L + c * 4);
        }
        float4 o = { tf32f(v.x), tf32f(v.y), tf32f(v.z), tf32f(v.w) };
        *(float4*)(dst + fidx_sw(m, c * 4)) = o;
    }
}

// ============================================================================
// Kernel 0c: At[kt] = swizzled tf32(Acat)   (64 rows per tile)
// ============================================================================
__global__ void __launch_bounds__(128)
convert_a_kernel(const float* __restrict__ Acat)
{
    const int tid = threadIdx.x;
    const int kt = blockIdx.x;
    float* dst = At + (size_t)kt * 1024;
    #pragma unroll
    for (int i = 0; i < 2; i++) {
        int idx = tid + i * 128;
        int m = idx >> 2, c = idx & 3;
        float4 v = *(const float4*)(Acat + (size_t)m * D_IN + kt * KC + c * 4);
        float4 o = { tf32f(v.x), tf32f(v.y), tf32f(v.z), tf32f(v.w) };
        *(float4*)(dst + fidx_sw(m, c * 4)) = o;
    }
}

// ============================================================================
// Kernel 1: LoRA activations -> Xt ktiles 80..83   [barrier-free, warp-private]
//   g[m][j] = scaling[j>>4]*mask[j>>4][m&4095] * (x[m].Acat[j])
//   128 thr, 128x64 CTA tile, 4 warps (2m x 2n), warp tile 64x32.
//   Per warp per stage: A-half 4KB + B-half 2KB, cp.async identity from Xt/At.
// ============================================================================
#define G_WSTG  1536                     /* floats per warp per stage (A 1024 + B 512) */
#define G_SSTG  (4 * G_WSTG)             /* 6144 floats per stage */
#define G_SMEM  (STAGES * G_SSTG * 4)    /* 73728 bytes */
__global__ void __launch_bounds__(128, 2)
lora_g_kernel(const float* __restrict__ scalings, const float* __restrict__ masks)
{
    extern __shared__ float sm[];
    const int tid  = threadIdx.x;
    const int mt   = blockIdx.x;
    const int mb   = mt * 128;
    const int lane = tid & 31;
    const int wid  = tid >> 5;
    const int gid  = lane >> 2, tig = lane & 3;
    const int moff = (wid & 1) * 64;
    const int noff = (wid >> 1) * 32;

    const uint32_t base = smem_u32(sm);
    const uint32_t wbase = base + (uint32_t)wid * (G_WSTG * 4);

    // ldmatrix per-lane addresses within warp-private buffers (stage 0)
    uint32_t aAddr[2], bAddr[2];
    {
        int sub  = lane & 15;
        int half = lane >> 4;
        #pragma unroll
        for (int ks = 0; ks < 2; ks++)
            aAddr[ks] = wbase + fidx_sw(sub, (2 * ks + half) * 4) * 4u;
        int nsub  = (lane & 7) + ((lane >> 4) << 3);
        int bhalf = (lane >> 3) & 1;
        #pragma unroll
        for (int ks = 0; ks < 2; ks++)
            bAddr[ks] = wbase + 4096u + fidx_sw(nsub, (2 * ks + bhalf) * 4) * 4u;
    }

    const float* srcA = Xt + (size_t)mt * NT_ALL * 2048 + moff * 16 + lane * 4;
    const float* srcB = At + noff * 16 + lane * 4;

    float acc[4][4][4];
    #pragma unroll
    for (int mi = 0; mi < 4; mi++)
        #pragma unroll
        for (int ni = 0; ni < 4; ni++)
            #pragma unroll
            for (int q = 0; q < 4; q++) acc[mi][ni][q] = 0.f;

    auto fill = [&](int t, int buf) {
        uint32_t d = wbase + (uint32_t)buf * (G_SSTG * 4) + (uint32_t)lane * 16u;
        const float* sa = srcA + (size_t)t * 2048;
        const float* sb = srcB + (size_t)t * 1024;
        #pragma unroll
        for (int i = 0; i < 8; i++) cp16(d + i * 512u, sa + i * 128);
        #pragma unroll
        for (int i = 0; i < 4; i++) cp16(d + 4096u + i * 512u, sb + i * 128);
    };
    auto domma = [&](int buf) {
        const uint32_t bo = (uint32_t)buf * (G_SSTG * 4);
        #pragma unroll
        for (int ks = 0; ks < 2; ks++) {
            uint32_t a[4][4], b[2][4];
            #pragma unroll
            for (int mi = 0; mi < 4; mi++)
                ldsm4(a[mi], aAddr[ks] + bo + (uint32_t)mi * 1024u);
            #pragma unroll
            for (int nj = 0; nj < 2; nj++)
                ldsm4(b[nj], bAddr[ks] + bo + (uint32_t)nj * 1024u);
            #pragma unroll
            for (int mi = 0; mi < 4; mi++)
                #pragma unroll
                for (int ni = 0; ni < 4; ni++)
                    mma_tf32(acc[mi][ni], a[mi][0], a[mi][1], a[mi][2], a[mi][3],
                             b[ni >> 1][(ni & 1) * 2], b[ni >> 1][(ni & 1) * 2 + 1]);
        }
    };

    #pragma unroll
    for (int t = 0; t < STAGES; t++) { fill(t, t); CP_COMMIT(); }
    for (int t = 0; t < NT_X; t++) {
        CP_WAIT2();
        int buf = t % STAGES;
        domma(buf);
        if (t + STAGES < NT_X) fill(t + STAGES, buf);
        CP_COMMIT();
    }

    // epilogue: coef = scaling * mask; tf32-round; store into Xt ktiles 80..83
    float coef[4][2][2];
    #pragma unroll
    for (int mi = 0; mi < 4; mi++)
        #pragma unroll
        for (int h = 0; h < 2; h++) {
            int m = mb + moff + mi * 16 + gid + h * 8;
            int s = m & (S_SZ - 1);
            #pragma unroll
            for (int sl = 0; sl < 2; sl++) {
                int subj = (noff >> 4) + sl;
                coef[mi][h][sl] = scalings[subj] * masks[subj * S_SZ + s];
            }
        }
    float* xblk = Xt + (size_t)mt * NT_ALL * 2048;
    #pragma unroll
    for (int mi = 0; mi < 4; mi++)
        #pragma unroll
        for (int ni = 0; ni < 4; ni++) {
            int col = noff + ni * 8 + 2 * tig;     // 0..63
            int sl  = ((ni * 8 + 2 * tig) >> 4) & 1;
            int kt  = NT_X + (col >> 4);
            int kk  = col & 15;
            #pragma unroll
            for (int h = 0; h < 2; h++) {
                int r = moff + mi * 16 + gid + h * 8;
                float2 v = { tf32f(acc[mi][ni][2 * h + 0] * coef[mi][h][sl]),
                             tf32f(acc[mi][ni][2 * h + 1] * coef[mi][h][sl]) };
                *(float2*)(xblk + (size_t)kt * 2048 + fidx_sw(r, kk)) = v;
            }
        }
}

// ============================================================================
// Kernel 2: out = [X|g] @ [W|Bcat]^T + bias   [barrier-free, warp-private]
//   128 thr, 128x128 CTA tile, 4 warps (2m x 2n), warp tile 64x64.
//   Per warp per stage: A-half 4KB + B-half 4KB, cp.async identity from Xt/Wt.
// ============================================================================
#define M_WSTG  2048                     /* floats per warp per stage */
#define M_SSTG  (4 * M_WSTG)             /* 8192 floats per stage */
#define M_SMEM  (STAGES * M_SSTG * 4)    /* 98304 bytes */
__global__ void __launch_bounds__(128, 2)
lora_main_kernel(const float* __restrict__ bias, float* __restrict__ out)
{
    extern __shared__ float sm[];
    const int tid  = threadIdx.x;
    const int nt   = blockIdx.x;          // x fastest: CTAs sharing mt hit Xt in L2
    const int mt   = blockIdx.y;
    const int lane = tid & 31;
    const int wid  = tid >> 5;
    const int gid  = lane >> 2, tig = lane & 3;
    const int moff = (wid & 1) * 64;
    const int noff = (wid >> 1) * 64;

    const uint32_t base = smem_u32(sm);
    const uint32_t wbase = base + (uint32_t)wid * (M_WSTG * 4);

    uint32_t aAddr[2], bAddr[2];
    {
        int sub  = lane & 15;
        int half = lane >> 4;
        #pragma unroll
        for (int ks = 0; ks < 2; ks++)
            aAddr[ks] = wbase + fidx_sw(sub, (2 * ks + half) * 4) * 4u;
        int nsub  = (lane & 7) + ((lane >> 4) << 3);
        int bhalf = (lane >> 3) & 1;
        #pragma unroll
        for (int ks = 0; ks < 2; ks++)
            bAddr[ks] = wbase + 4096u + fidx_sw(nsub, (2 * ks + bhalf) * 4) * 4u;
    }

    const float* srcA = Xt + (size_t)mt * NT_ALL * 2048 + moff * 16 + lane * 4;
    const float* srcB = Wt + (size_t)nt * NT_ALL * 2048 + noff * 16 + lane * 4;

    float acc[4][8][4];
    #pragma unroll
    for (int mi = 0; mi < 4; mi++)
        #pragma unroll
        for (int ni = 0; ni < 8; ni++)
            #pragma unroll
            for (int q = 0; q < 4; q++) acc[mi][ni][q] = 0.f;

    auto fill = [&](int t, int buf) {
        uint32_t d = wbase + (uint32_t)buf * (M_SSTG * 4) + (uint32_t)lane * 16u;
        const float* sa = srcA + (size_t)t * 2048;
        const float* sb = srcB + (size_t)t * 2048;
        #pragma unroll
        for (int i = 0; i < 8; i++) {
            cp16(d + i * 512u, sa + i * 128);
            cp16(d + 4096u + i * 512u, sb + i * 128);
        }
    };
    auto domma = [&](int buf) {
        const uint32_t bo = (uint32_t)buf * (M_SSTG * 4);
        #pragma unroll
        for (int ks = 0; ks < 2; ks++) {
            uint32_t a[4][4], b[4][4];
            #pragma unroll
            for (int mi = 0; mi < 4; mi++)
                ldsm4(a[mi], aAddr[ks] + bo + (uint32_t)mi * 1024u);
            #pragma unroll
            for (int nj = 0; nj < 4; nj++)
                ldsm4(b[nj], bAddr[ks] + bo + (uint32_t)nj * 1024u);
            #pragma unroll
            for (int mi = 0; mi < 4; mi++)
                #pragma unroll
                for (int ni = 0; ni < 8; ni++)
                    mma_tf32(acc[mi][ni], a[mi][0], a[mi][1], a[mi][2], a[mi][3],
                             b[ni >> 1][(ni & 1) * 2], b[ni >> 1][(ni & 1) * 2 + 1]);
        }
    };

    #pragma unroll
    for (int t = 0; t < STAGES; t++) { fill(t, t); CP_COMMIT(); }
    for (int t = 0; t < NT_ALL; t++) {
        CP_WAIT2();
        int buf = t % STAGES;
        domma(buf);
        if (t + STAGES < NT_ALL) fill(t + STAGES, buf);
        CP_COMMIT();
    }

    // epilogue: + bias, float2 stores
    const int nb = nt * 128, mb = mt * 128;
    #pragma unroll
    for (int ni = 0; ni < 8; ni++) {
        int col = nb + noff + ni * 8 + 2 * tig;
        float2 bb = *(const float2*)(bias + col);
        #pragma unroll
        for (int mi = 0; mi < 4; mi++) {
            int row0 = mb + moff + mi * 16 + gid;
            float2 v0 = { acc[mi][ni][0] + bb.x, acc[mi][ni][1] + bb.y };
            float2 v1 = { acc[mi][ni][2] + bb.x, acc[mi][ni][3] + bb.y };
            *(float2*)(out + (size_t)row0 * D_OUT + col)       = v0;
            *(float2*)(out + (size_t)(row0 + 8) * D_OUT + col) = v1;
        }
    }
}

// ============================================================================
extern "C" void kernel_launch(void* const* d_in, const int* in_sizes, int n_in,
                              void* d_out, int out_size)
{
    (void)in_sizes; (void)n_in; (void)out_size;
    const float* X     = (const float*)d_in[0];
    const float* W     = (const float*)d_in[1];
    const float* bias  = (const float*)d_in[2];
    const float* Acat  = (const float*)d_in[3];   // (N,R,D) flattens to (64,1280)
    const float* Bw    = (const float*)d_in[4];
    const float* scal  = (const float*)d_in[5];
    const float* masks = (const float*)d_in[6];
    float* out = (float*)d_out;

    static int attr_done = 0;
    if (!attr_done) {
        cudaFuncSetAttribute(lora_g_kernel,
                             cudaFuncAttributeMaxDynamicSharedMemorySize, G_SMEM);
        cudaFuncSetAttribute(lora_main_kernel,
                             cudaFuncAttributeMaxDynamicSharedMemorySize, M_SMEM);
        attr_done = 1;
    }

    convert_x_kernel<<<dim3(M_ROWS / 128, NT_X), 128>>>(X);
    convert_w_kernel<<<dim3(D_OUT / 128, NT_ALL), 128>>>(W, Bw);
    convert_a_kernel<<<NT_X, 128>>>(Acat);
    lora_g_kernel<<<M_ROWS / 128, 128, G_SMEM>>>(scal, masks);
    lora_main_kernel<<<dim3(D_OUT / 128, M_ROWS / 128), 128, M_SMEM>>>(bias, out);
}

// round 10
// speedup vs baseline: 1.3747x; 1.3747x over previous
#include <cuda_runtime.h>
#include <cstdint>

#define DEVINL __device__ __forceinline__

// ---------------- problem dims ----------------
#define B_SZ   8
#define S_SZ   4096
#define D_IN   1280
#define D_OUT  1280
#define N_L    4
#define R_L    16
#define J_L    64                 /* N_L * R_L */
#define M_ROWS 32768              /* B_SZ * S_SZ */
#define K_TOT  1344               /* D_IN + J_L  */

// ---------------- tiling ----------------
#define KC      16                /* K per ktile unit */
#define NT_ALL  (K_TOT / KC)      /* 84 ktiles */
#define NT_X    (D_IN / KC)       /* 80 */
#define NT2     (NT_ALL / 2)      /* 42 macro-stages (KC=32) in main kernel */
#define STAGES_G 3                /* g-kernel pipeline depth */
#define STAGES_M 3                /* main-kernel macro-stage depth */

// Pre-swizzled, tf32-pre-rounded operand tensors.
//   Xt[mtile][ktile][2048]  (mtile = m>>7), Wt[ntile][ktile][2048]
//   At[ktile][1024]  (Acat, 64 rows)
// In-tile layout (m, kk = k&15):
//   fidx(m,kk) = (m>>1)*32 + (((4*(m&1) + (kk>>2)) ^ ((m>>1)&7)) << 2) + (kk&3)
// Halves self-contained: rows [0,64) -> floats [0,1024), rows [64,128) -> [1024,2048).
__device__ float Xt[(size_t)(M_ROWS / 128) * NT_ALL * 2048];
__device__ float Wt[(size_t)(D_OUT / 128) * NT_ALL * 2048];
__device__ float At[(size_t)NT_X * 1024];

// ---------------- helpers ----------------
DEVINL uint32_t tf32b(float x) {
    uint32_t r;
    asm("cvt.rna.tf32.f32 %0, %1;" : "=r"(r) : "f"(x));
    return r;
}
DEVINL float tf32f(float x) { uint32_t r = tf32b(x); return __uint_as_float(r); }

DEVINL void mma_tf32(float c[4], uint32_t a0, uint32_t a1, uint32_t a2, uint32_t a3,
                     uint32_t b0, uint32_t b1) {
    asm volatile(
        "mma.sync.aligned.m16n8k8.row.col.f32.tf32.tf32.f32 "
        "{%0,%1,%2,%3}, {%4,%5,%6,%7}, {%8,%9}, {%0,%1,%2,%3};"
        : "+f"(c[0]), "+f"(c[1]), "+f"(c[2]), "+f"(c[3])
        : "r"(a0), "r"(a1), "r"(a2), "r"(a3), "r"(b0), "r"(b1));
}
DEVINL void ldsm4(uint32_t r[4], uint32_t addr) {
    asm volatile("ldmatrix.sync.aligned.m8n8.x4.shared.b16 {%0,%1,%2,%3}, [%4];"
                 : "=r"(r[0]), "=r"(r[1]), "=r"(r[2]), "=r"(r[3]) : "r"(addr));
}
DEVINL uint32_t smem_u32(const void* p) {
    uint32_t a;
    asm("{ .reg .u64 t; cvta.to.shared.u64 t, %1; cvt.u32.u64 %0, t; }" : "=r"(a) : "l"(p));
    return a;
}
DEVINL void cp16(uint32_t smem, const void* gptr) {
    asm volatile("cp.async.cg.shared.global [%0], [%1], 16;" :: "r"(smem), "l"(gptr) : "memory");
}
#define CP_COMMIT() asm volatile("cp.async.commit_group;" ::: "memory")
#define CP_WAIT1()  asm volatile("cp.async.wait_group 1;" ::: "memory")
#define CP_WAIT2()  asm volatile("cp.async.wait_group 2;" ::: "memory")

DEVINL uint32_t fidx_sw(int m, int kk) {
    int p = m >> 1, q = m & 1;
    return (uint32_t)(p * 32 + (((4 * q + (kk >> 2)) ^ (p & 7)) << 2) + (kk & 3));
}

// ============================================================================
// Kernel 0a: Xt[mt][kt<80] = swizzled tf32(X)
// ============================================================================
__global__ void __launch_bounds__(128)
convert_x_kernel(const float* __restrict__ X)
{
    const int tid = threadIdx.x;
    const int mt = blockIdx.x, kt = blockIdx.y;
    float* dst = Xt + ((size_t)mt * NT_ALL + kt) * 2048;
    #pragma unroll
    for (int i = 0; i < 4; i++) {
        int idx = tid + i * 128;
        int m = idx >> 2, c = idx & 3;
        float4 v = *(const float4*)(X + (size_t)(mt * 128 + m) * D_IN + kt * KC + c * 4);
        float4 o = { tf32f(v.x), tf32f(v.y), tf32f(v.z), tf32f(v.w) };
        *(float4*)(dst + fidx_sw(m, c * 4)) = o;
    }
}

// ============================================================================
// Kernel 0b: Wt[nt][kt] from W (kt<80) / Bcat gather (kt>=80)
//   Bcat[o][j] = Bw[j>>4][o][j&15]
// ============================================================================
__global__ void __launch_bounds__(128)
convert_w_kernel(const float* __restrict__ W, const float* __restrict__ Bw)
{
    const int tid = threadIdx.x;
    const int nt = blockIdx.x, kt = blockIdx.y;
    float* dst = Wt + ((size_t)nt * NT_ALL + kt) * 2048;
    #pragma unroll
    for (int i = 0; i < 4; i++) {
        int idx = tid + i * 128;
        int m = idx >> 2, c = idx & 3;
        float4 v;
        if (kt < NT_X) {
            v = *(const float4*)(W + (size_t)(nt * 128 + m) * D_IN + kt * KC + c * 4);
        } else {
            v = *(const float4*)(Bw + (size_t)(kt - NT_X) * (D_OUT * R_L)
                                    + (size_t)(nt * 128 + m) * R_L + c * 4);
        }
        float4 o = { tf32f(v.x), tf32f(v.y), tf32f(v.z), tf32f(v.w) };
        *(float4*)(dst + fidx_sw(m, c * 4)) = o;
    }
}

// ============================================================================
// Kernel 0c: At[kt] = swizzled tf32(Acat)   (64 rows per tile)
// ============================================================================
__global__ void __launch_bounds__(128)
convert_a_kernel(const float* __restrict__ Acat)
{
    const int tid = threadIdx.x;
    const int kt = blockIdx.x;
    float* dst = At + (size_t)kt * 1024;
    #pragma unroll
    for (int i = 0; i < 2; i++) {
        int idx = tid + i * 128;
        int m = idx >> 2, c = idx & 3;
        float4 v = *(const float4*)(Acat + (size_t)m * D_IN + kt * KC + c * 4);
        float4 o = { tf32f(v.x), tf32f(v.y), tf32f(v.z), tf32f(v.w) };
        *(float4*)(dst + fidx_sw(m, c * 4)) = o;
    }
}

// ============================================================================
// Kernel 1: LoRA activations -> Xt ktiles 80..83   [barrier-free, warp-private]
//   (R9 version — measured 52.7us, kept as-is)
// ============================================================================
#define G_WSTG  1536
#define G_SSTG  (4 * G_WSTG)
#define G_SMEM  (STAGES_G * G_SSTG * 4)
__global__ void __launch_bounds__(128, 2)
lora_g_kernel(const float* __restrict__ scalings, const float* __restrict__ masks)
{
    extern __shared__ float sm[];
    const int tid  = threadIdx.x;
    const int mt   = blockIdx.x;
    const int mb   = mt * 128;
    const int lane = tid & 31;
    const int wid  = tid >> 5;
    const int gid  = lane >> 2, tig = lane & 3;
    const int moff = (wid & 1) * 64;
    const int noff = (wid >> 1) * 32;

    const uint32_t base = smem_u32(sm);
    const uint32_t wbase = base + (uint32_t)wid * (G_WSTG * 4);

    uint32_t aAddr[2], bAddr[2];
    {
        int sub  = lane & 15;
        int half = lane >> 4;
        #pragma unroll
        for (int ks = 0; ks < 2; ks++)
            aAddr[ks] = wbase + fidx_sw(sub, (2 * ks + half) * 4) * 4u;
        int nsub  = (lane & 7) + ((lane >> 4) << 3);
        int bhalf = (lane >> 3) & 1;
        #pragma unroll
        for (int ks = 0; ks < 2; ks++)
            bAddr[ks] = wbase + 4096u + fidx_sw(nsub, (2 * ks + bhalf) * 4) * 4u;
    }

    const float* srcA = Xt + (size_t)mt * NT_ALL * 2048 + moff * 16 + lane * 4;
    const float* srcB = At + noff * 16 + lane * 4;

    float acc[4][4][4];
    #pragma unroll
    for (int mi = 0; mi < 4; mi++)
        #pragma unroll
        for (int ni = 0; ni < 4; ni++)
            #pragma unroll
            for (int q = 0; q < 4; q++) acc[mi][ni][q] = 0.f;

    auto fill = [&](int t, int buf) {
        uint32_t d = wbase + (uint32_t)buf * (G_SSTG * 4) + (uint32_t)lane * 16u;
        const float* sa = srcA + (size_t)t * 2048;
        const float* sb = srcB + (size_t)t * 1024;
        #pragma unroll
        for (int i = 0; i < 8; i++) cp16(d + i * 512u, sa + i * 128);
        #pragma unroll
        for (int i = 0; i < 4; i++) cp16(d + 4096u + i * 512u, sb + i * 128);
    };
    auto domma = [&](int buf) {
        const uint32_t bo = (uint32_t)buf * (G_SSTG * 4);
        #pragma unroll
        for (int ks = 0; ks < 2; ks++) {
            uint32_t a[4][4], b[2][4];
            #pragma unroll
            for (int mi = 0; mi < 4; mi++)
                ldsm4(a[mi], aAddr[ks] + bo + (uint32_t)mi * 1024u);
            #pragma unroll
            for (int nj = 0; nj < 2; nj++)
                ldsm4(b[nj], bAddr[ks] + bo + (uint32_t)nj * 1024u);
            #pragma unroll
            for (int mi = 0; mi < 4; mi++)
                #pragma unroll
                for (int ni = 0; ni < 4; ni++)
                    mma_tf32(acc[mi][ni], a[mi][0], a[mi][1], a[mi][2], a[mi][3],
                             b[ni >> 1][(ni & 1) * 2], b[ni >> 1][(ni & 1) * 2 + 1]);
        }
    };

    #pragma unroll
    for (int t = 0; t < STAGES_G; t++) { fill(t, t); CP_COMMIT(); }
    for (int t = 0; t < NT_X; t++) {
        CP_WAIT2();
        int buf = t % STAGES_G;
        domma(buf);
        if (t + STAGES_G < NT_X) fill(t + STAGES_G, buf);
        CP_COMMIT();
    }

    float coef[4][2][2];
    #pragma unroll
    for (int mi = 0; mi < 4; mi++)
        #pragma unroll
        for (int h = 0; h < 2; h++) {
            int m = mb + moff + mi * 16 + gid + h * 8;
            int s = m & (S_SZ - 1);
            #pragma unroll
            for (int sl = 0; sl < 2; sl++) {
                int subj = (noff >> 4) + sl;
                coef[mi][h][sl] = scalings[subj] * masks[subj * S_SZ + s];
            }
        }
    float* xblk = Xt + (size_t)mt * NT_ALL * 2048;
    #pragma unroll
    for (int mi = 0; mi < 4; mi++)
        #pragma unroll
        for (int ni = 0; ni < 4; ni++) {
            int col = noff + ni * 8 + 2 * tig;
            int sl  = ((ni * 8 + 2 * tig) >> 4) & 1;
            int kt  = NT_X + (col >> 4);
            int kk  = col & 15;
            #pragma unroll
            for (int h = 0; h < 2; h++) {
                int r = moff + mi * 16 + gid + h * 8;
                float2 v = { tf32f(acc[mi][ni][2 * h + 0] * coef[mi][h][sl]),
                             tf32f(acc[mi][ni][2 * h + 1] * coef[mi][h][sl]) };
                *(float2*)(xblk + (size_t)kt * 2048 + fidx_sw(r, kk)) = v;
            }
        }
}

// ============================================================================
// Kernel 2: out = [X|g] @ [W|Bcat]^T + bias   (K = 1344)
//   128 thr, 128x128 tile, 4 warps (2m x 2n), warp tile 64x64.
//   CTA-shared buffers (R8 traffic), KC=32 macro-stages (half the barriers),
//   3-deep cp.async pipeline, 96KB dynamic smem, 2 CTAs/SM.
// ============================================================================
#define M_STG_FL  8192                       /* floats per macro-stage (A 4096 + B 4096) */
#define M_SMEM    (STAGES_M * M_STG_FL * 4)  /* 98304 bytes */
__global__ void __launch_bounds__(128, 2)
lora_main_kernel(const float* __restrict__ bias, float* __restrict__ out)
{
    extern __shared__ float sm[];
    const int tid  = threadIdx.x;
    const int nt   = blockIdx.x;          // x fastest: CTAs sharing mt hit Xt in L2
    const int mt   = blockIdx.y;
    const int lane = tid & 31;
    const int wid  = tid >> 5;
    const int gid  = lane >> 2, tig = lane & 3;
    const int moff = (wid & 1) * 64;
    const int noff = (wid >> 1) * 64;

    // stage layout: [A ktile even 2048][A ktile odd 2048][B even 2048][B odd 2048]
    const uint32_t base = smem_u32(sm);

    // ldmatrix per-lane addresses within one 2048-float ktile (stage 0, unit 0)
    uint32_t aAddr[2], bAddr[2];
    {
        int sub  = lane & 15;
        int half = lane >> 4;
        #pragma unroll
        for (int ks = 0; ks < 2; ks++)
            aAddr[ks] = base + fidx_sw(moff + sub, (2 * ks + half) * 4) * 4u;
        int nsub  = (lane & 7) + ((lane >> 4) << 3);
        int bhalf = (lane >> 3) & 1;
        #pragma unroll
        for (int ks = 0; ks < 2; ks++)
            bAddr[ks] = base + 16384u + fidx_sw(noff + nsub, (2 * ks + bhalf) * 4) * 4u;
    }

    const float* srcA = Xt + (size_t)mt * NT_ALL * 2048 + tid * 4;   // ktile-contig
    const float* srcB = Wt + (size_t)nt * NT_ALL * 2048 + tid * 4;

    float acc[4][8][4];
    #pragma unroll
    for (int mi = 0; mi < 4; mi++)
        #pragma unroll
        for (int ni = 0; ni < 8; ni++)
            #pragma unroll
            for (int q = 0; q < 4; q++) acc[mi][ni][q] = 0.f;

    auto fill = [&](int t2, int buf) {       // copies ktiles 2*t2, 2*t2+1
        uint32_t d = base + (uint32_t)buf * (M_STG_FL * 4) + (uint32_t)tid * 16u;
        const float* sa = srcA + (size_t)t2 * 4096;
        const float* sb = srcB + (size_t)t2 * 4096;
        #pragma unroll
        for (int i = 0; i < 8; i++) {        // A: 4096 floats
            cp16(d + i * 2048u, sa + i * 512);
            cp16(d + 16384u + i * 2048u, sb + i * 512);  // B: 4096 floats
        }
    };
    auto domma = [&](int buf) {
        const uint32_t bo = (uint32_t)buf * (M_STG_FL * 4);
        #pragma unroll
        for (int u = 0; u < 2; u++) {        // ktile unit within macro-stage
            const uint32_t uo = bo + (uint32_t)u * 8192u;
            #pragma unroll
            for (int ks = 0; ks < 2; ks++) {
                uint32_t a[4][4], b[4][4];
                #pragma unroll
                for (int mi = 0; mi < 4; mi++)
                    ldsm4(a[mi], aAddr[ks] + uo + (uint32_t)mi * 1024u);
                #pragma unroll
                for (int nj = 0; nj < 4; nj++)
                    ldsm4(b[nj], bAddr[ks] + uo + (uint32_t)nj * 1024u);
                #pragma unroll
                for (int mi = 0; mi < 4; mi++)
                    #pragma unroll
                    for (int ni = 0; ni < 8; ni++)
                        mma_tf32(acc[mi][ni], a[mi][0], a[mi][1], a[mi][2], a[mi][3],
                                 b[ni >> 1][(ni & 1) * 2], b[ni >> 1][(ni & 1) * 2 + 1]);
            }
        }
    };

    fill(0, 0); CP_COMMIT();
    fill(1, 1); CP_COMMIT();
    for (int t2 = 0; t2 < NT2; t2++) {
        CP_WAIT1();                          // group t2 complete (own thread)
        __syncthreads();                     // all threads' stage-t2 data visible
        if (t2 + 2 < NT2) fill(t2 + 2, (t2 + 2) % STAGES_M);
        CP_COMMIT();
        domma(t2 % STAGES_M);
    }

    // epilogue: + bias, float2 stores
    const int nb = nt * 128, mb = mt * 128;
    #pragma unroll
    for (int ni = 0; ni < 8; ni++) {
        int col = nb + noff + ni * 8 + 2 * tig;
        float2 bb = *(const float2*)(bias + col);
        #pragma unroll
        for (int mi = 0; mi < 4; mi++) {
            int row0 = mb + moff + mi * 16 + gid;
            float2 v0 = { acc[mi][ni][0] + bb.x, acc[mi][ni][1] + bb.y };
            float2 v1 = { acc[mi][ni][2] + bb.x, acc[mi][ni][3] + bb.y };
            *(float2*)(out + (size_t)row0 * D_OUT + col)       = v0;
            *(float2*)(out + (size_t)(row0 + 8) * D_OUT + col) = v1;
        }
    }
}

// ============================================================================
extern "C" void kernel_launch(void* const* d_in, const int* in_sizes, int n_in,
                              void* d_out, int out_size)
{
    (void)in_sizes; (void)n_in; (void)out_size;
    const float* X     = (const float*)d_in[0];
    const float* W     = (const float*)d_in[1];
    const float* bias  = (const float*)d_in[2];
    const float* Acat  = (const float*)d_in[3];   // (N,R,D) flattens to (64,1280)
    const float* Bw    = (const float*)d_in[4];
    const float* scal  = (const float*)d_in[5];
    const float* masks = (const float*)d_in[6];
    float* out = (float*)d_out;

    cudaFuncSetAttribute(lora_g_kernel,
                         cudaFuncAttributeMaxDynamicSharedMemorySize, G_SMEM);
    cudaFuncSetAttribute(lora_main_kernel,
                         cudaFuncAttributeMaxDynamicSharedMemorySize, M_SMEM);

    convert_x_kernel<<<dim3(M_ROWS / 128, NT_X), 128>>>(X);
    convert_w_kernel<<<dim3(D_OUT / 128, NT_ALL), 128>>>(W, Bw);
    convert_a_kernel<<<NT_X, 128>>>(Acat);
    lora_g_kernel<<<M_ROWS / 128, 128, G_SMEM>>>(scal, masks);
    lora_main_kernel<<<dim3(D_OUT / 128, M_ROWS / 128), 128, M_SMEM>>>(bias, out);
}

// round 12
// speedup vs baseline: 2.4464x; 1.7796x over previous
#include <cuda_runtime.h>
#include <cuda_fp16.h>
#include <cstdint>

#define DEVINL __device__ __forceinline__

// ---------------- problem dims ----------------
#define B_SZ   8
#define S_SZ   4096
#define D_IN   1280
#define D_OUT  1280
#define N_L    4
#define R_L    16
#define J_L    64                 /* N_L * R_L */
#define M_ROWS 32768              /* B_SZ * S_SZ */
#define K_TOT  1344               /* D_IN + J_L  */

// ---------------- tiling ----------------
#define KU      16                /* K per unit ktile */
#define NTU     (K_TOT / KU)      /* 84 unit ktiles */
#define NTU_X   (D_IN / KU)       /* 80 */
#define NTM     (NTU / 4)         /* 21 macro-stages (KC=64) in main kernel */
#define STAGES_M 3
#define STAGES_G 4

// Pre-swizzled fp16 operand tensors.
//   Xh[mtile][unit][2048 halves] (4KB tiles), Wh[ntile][unit][2048], Ah[unit][1024]
// 16B-chunk layout inside a tile (m = row, h = k>>3):
//   byte = (m>>2)*128 + (((m&3)*2 + (h ^ ((m>>2)&1))) * 16)
// Conflict-free for ldmatrix.x4 and identity cp.async; +16 rows => +512B (parity kept).
__device__ __half Xh[(size_t)(M_ROWS / 128) * NTU * 2048];
__device__ __half Wh[(size_t)(D_OUT / 128) * NTU * 2048];
__device__ __half Ah[(size_t)NTU_X * 1024];

// ---------------- helpers ----------------
DEVINL uint32_t cofs(int m, int h) {      // 16B-chunk byte offset within one tile
    int line = m >> 2;
    int slot = ((m & 3) * 2) + (h ^ (line & 1));
    return (uint32_t)(line * 128 + slot * 16);
}
DEVINL uint32_t pack2h(float a, float b) {
    __half2 h = __floats2half2_rn(a, b);
    return *reinterpret_cast<uint32_t*>(&h);
}
DEVINL void mma_f16(float c[4], uint32_t a0, uint32_t a1, uint32_t a2, uint32_t a3,
                    uint32_t b0, uint32_t b1) {
    asm volatile(
        "mma.sync.aligned.m16n8k16.row.col.f32.f16.f16.f32 "
        "{%0,%1,%2,%3}, {%4,%5,%6,%7}, {%8,%9}, {%0,%1,%2,%3};"
        : "+f"(c[0]), "+f"(c[1]), "+f"(c[2]), "+f"(c[3])
        : "r"(a0), "r"(a1), "r"(a2), "r"(a3), "r"(b0), "r"(b1));
}
DEVINL void ldsm4(uint32_t r[4], uint32_t addr) {
    asm volatile("ldmatrix.sync.aligned.m8n8.x4.shared.b16 {%0,%1,%2,%3}, [%4];"
                 : "=r"(r[0]), "=r"(r[1]), "=r"(r[2]), "=r"(r[3]) : "r"(addr));
}
DEVINL uint32_t smem_u32(const void* p) {
    uint32_t a;
    asm("{ .reg .u64 t; cvta.to.shared.u64 t, %1; cvt.u32.u64 %0, t; }" : "=r"(a) : "l"(p));
    return a;
}
DEVINL void cp16(uint32_t smem, const void* gptr) {
    asm volatile("cp.async.cg.shared.global [%0], [%1], 16;" :: "r"(smem), "l"(gptr) : "memory");
}
#define CP_COMMIT() asm volatile("cp.async.commit_group;" ::: "memory")
#define CP_WAIT1()  asm volatile("cp.async.wait_group 1;" ::: "memory")
#define CP_WAIT2()  asm volatile("cp.async.wait_group 2;" ::: "memory")

// ============================================================================
// Kernel 0a: Xh[mt][kt<80] = swizzled fp16(X)     grid (256, 80), 128 thr
// ============================================================================
__global__ void __launch_bounds__(128)
convert_x_kernel(const float* __restrict__ X)
{
    const int tid = threadIdx.x;
    const int mt = blockIdx.x, kt = blockIdx.y;
    char* dst = (char*)(Xh + ((size_t)mt * NTU + kt) * 2048);
    #pragma unroll
    for (int i = 0; i < 2; i++) {
        int idx = tid + i * 128;
        int m = idx >> 1, h = idx & 1;
        const float4* p = (const float4*)(X + (size_t)(mt * 128 + m) * D_IN + kt * KU + h * 8);
        float4 v0 = p[0], v1 = p[1];
        uint4 o = { pack2h(v0.x, v0.y), pack2h(v0.z, v0.w),
                    pack2h(v1.x, v1.y), pack2h(v1.z, v1.w) };
        *(uint4*)(dst + cofs(m, h)) = o;
    }
}

// ============================================================================
// Kernel 0b: Wh[nt][kt] from W (kt<80) / Bcat gather (kt>=80)   grid (10, 84)
//   Bcat[o][j] = Bw[j>>4][o][j&15]
// ============================================================================
__global__ void __launch_bounds__(128)
convert_w_kernel(const float* __restrict__ W, const float* __restrict__ Bw)
{
    const int tid = threadIdx.x;
    const int nt = blockIdx.x, kt = blockIdx.y;
    char* dst = (char*)(Wh + ((size_t)nt * NTU + kt) * 2048);
    #pragma unroll
    for (int i = 0; i < 2; i++) {
        int idx = tid + i * 128;
        int m = idx >> 1, h = idx & 1;
        const float4* p;
        if (kt < NTU_X) {
            p = (const float4*)(W + (size_t)(nt * 128 + m) * D_IN + kt * KU + h * 8);
        } else {
            p = (const float4*)(Bw + (size_t)(kt - NTU_X) * (D_OUT * R_L)
                                   + (size_t)(nt * 128 + m) * R_L + h * 8);
        }
        float4 v0 = p[0], v1 = p[1];
        uint4 o = { pack2h(v0.x, v0.y), pack2h(v0.z, v0.w),
                    pack2h(v1.x, v1.y), pack2h(v1.z, v1.w) };
        *(uint4*)(dst + cofs(m, h)) = o;
    }
}

// ============================================================================
// Kernel 0c: Ah[kt] = swizzled fp16(Acat)   (64 rows per tile)   grid (80)
// ============================================================================
__global__ void __launch_bounds__(128)
convert_a_kernel(const float* __restrict__ Acat)
{
    const int tid = threadIdx.x;
    const int kt = blockIdx.x;
    char* dst = (char*)(Ah + (size_t)kt * 1024);
    int m = tid >> 1, h = tid & 1;
    const float4* p = (const float4*)(Acat + (size_t)m * D_IN + kt * KU + h * 8);
    float4 v0 = p[0], v1 = p[1];
    uint4 o = { pack2h(v0.x, v0.y), pack2h(v0.z, v0.w),
                pack2h(v1.x, v1.y), pack2h(v1.z, v1.w) };
    *(uint4*)(dst + cofs(m, h)) = o;
}

// ============================================================================
// Kernel 1: LoRA activations -> Xh ktiles 80..83   [barrier-free, warp-private]
//   g[m][j] = scaling[j>>4]*mask[j>>4][m&4095] * (x[m].Acat[j]), fp16-rounded.
//   128 thr, 128x64 CTA tile, 4 warps (2m x 2n), warp tile 64x32, fp16 MMA.
// ============================================================================
#define G_WB   3072                     /* bytes per warp per stage: A 2KB + B 1KB */
#define G_SB   (4 * G_WB)               /* 12288 per stage */
#define G_SMEM (STAGES_G * G_SB)        /* 49152 */
__global__ void __launch_bounds__(128, 2)
lora_g_kernel(const float* __restrict__ scalings, const float* __restrict__ masks)
{
    extern __shared__ char smc[];
    const int tid  = threadIdx.x;
    const int mt   = blockIdx.x;
    const int mb   = mt * 128;
    const int lane = tid & 31;
    const int wid  = tid >> 5;
    const int gid  = lane >> 2, tig = lane & 3;
    const int moff = (wid & 1) * 64;
    const int noff = (wid >> 1) * 32;
    const int r8   = lane & 7, g8 = lane >> 3;

    const uint32_t base  = smem_u32(smc);
    const uint32_t wbase = base + (uint32_t)wid * G_WB;
    const uint32_t aAddr0 = wbase + cofs(r8 + (g8 & 1) * 8, g8 >> 1);
    const uint32_t bAddr0 = wbase + 2048u + cofs(r8 + (g8 >> 1) * 8, g8 & 1);

    const __half* srcA = Xh + (size_t)mt * NTU * 2048 + moff * 16 + lane * 8;
    const __half* srcB = Ah + noff * 16 + lane * 8;

    float acc[4][4][4];
    #pragma unroll
    for (int mi = 0; mi < 4; mi++)
        #pragma unroll
        for (int ni = 0; ni < 4; ni++)
            #pragma unroll
            for (int q = 0; q < 4; q++) acc[mi][ni][q] = 0.f;

    auto fill = [&](int t, int buf) {
        uint32_t d = wbase + (uint32_t)buf * G_SB + (uint32_t)lane * 16u;
        const __half* sa = srcA + (size_t)t * 2048;
        const __half* sb = srcB + (size_t)t * 1024;
        #pragma unroll
        for (int i = 0; i < 4; i++) cp16(d + i * 512u, sa + i * 256);
        #pragma unroll
        for (int i = 0; i < 2; i++) cp16(d + 2048u + i * 512u, sb + i * 256);
    };
    auto domma = [&](int buf) {
        const uint32_t bo = (uint32_t)buf * G_SB;
        uint32_t a[4][4], b[2][4];
        #pragma unroll
        for (int mi = 0; mi < 4; mi++) ldsm4(a[mi], aAddr0 + bo + (uint32_t)mi * 512u);
        #pragma unroll
        for (int nj = 0; nj < 2; nj++) ldsm4(b[nj], bAddr0 + bo + (uint32_t)nj * 512u);
        #pragma unroll
        for (int mi = 0; mi < 4; mi++)
            #pragma unroll
            for (int ni = 0; ni < 4; ni++)
                mma_f16(acc[mi][ni], a[mi][0], a[mi][1], a[mi][2], a[mi][3],
                        b[ni >> 1][(ni & 1) * 2], b[ni >> 1][(ni & 1) * 2 + 1]);
    };

    #pragma unroll
    for (int t = 0; t < STAGES_G; t++) { fill(t, t); CP_COMMIT(); }
    for (int t = 0; t < NTU_X; t++) {
        CP_WAIT2();
        domma(t & 3);
        if (t + STAGES_G < NTU_X) fill(t + STAGES_G, t & 3);
        CP_COMMIT();
    }

    // epilogue: coef = scaling * mask, fp16-round, store into Xh ktiles 80..83
    float coef[4][2][2];
    #pragma unroll
    for (int mi = 0; mi < 4; mi++)
        #pragma unroll
        for (int h = 0; h < 2; h++) {
            int m = mb + moff + mi * 16 + gid + h * 8;
            int s = m & (S_SZ - 1);
            #pragma unroll
            for (int sl = 0; sl < 2; sl++) {
                int subj = (noff >> 4) + sl;
                coef[mi][h][sl] = scalings[subj] * masks[subj * S_SZ + s];
            }
        }
    char* xblk = (char*)(Xh + (size_t)mt * NTU * 2048);
    #pragma unroll
    for (int mi = 0; mi < 4; mi++)
        #pragma unroll
        for (int ni = 0; ni < 4; ni++) {
            int col = noff + ni * 8 + 2 * tig;     // 0..63
            int sl  = ((ni * 8 + 2 * tig) >> 4) & 1;
            int kt  = NTU_X + (col >> 4);
            int kk  = col & 15;
            #pragma unroll
            for (int h = 0; h < 2; h++) {
                int rr = moff + mi * 16 + gid + h * 8;
                uint32_t v = pack2h(acc[mi][ni][2 * h + 0] * coef[mi][h][sl],
                                    acc[mi][ni][2 * h + 1] * coef[mi][h][sl]);
                *(uint32_t*)(xblk + (size_t)kt * 4096 + cofs(rr, kk >> 3) + (kk & 7) * 2) = v;
            }
        }
}

// ============================================================================
// Kernel 2: out = [X|g] @ [W|Bcat]^T + bias   (K = 1344, fp16 MMA)
//   128 thr, 128x128 tile, 4 warps (2m x 2n), warp tile 64x64.
//   KC=64 macro-stages (21 total), 3-deep, 96KB dynamic smem, 2 CTAs/SM.
// ============================================================================
#define M_STG_B  32768                        /* bytes per macro-stage (A 16KB + B 16KB) */
#define M_SMEM   (STAGES_M * M_STG_B)         /* 98304 */
__global__ void __launch_bounds__(128, 2)
lora_main_kernel(const float* __restrict__ bias, float* __restrict__ out)
{
    extern __shared__ char smc[];
    const int tid  = threadIdx.x;
    const int nt   = blockIdx.x;          // x fastest: CTAs sharing mt hit Xh in L2
    const int mt   = blockIdx.y;
    const int lane = tid & 31;
    const int wid  = tid >> 5;
    const int gid  = lane >> 2, tig = lane & 3;
    const int moff = (wid & 1) * 64;
    const int noff = (wid >> 1) * 64;
    const int r8   = lane & 7, g8 = lane >> 3;

    const uint32_t base = smem_u32(smc);
    // stage layout: [A: 4 unit tiles, 16KB][B: 4 unit tiles, 16KB]
    const uint32_t aAddr0 = base + cofs(moff + r8 + (g8 & 1) * 8, g8 >> 1);
    const uint32_t bAddr0 = base + 16384u + cofs(noff + r8 + (g8 >> 1) * 8, g8 & 1);

    const __half* srcA = Xh + (size_t)mt * NTU * 2048 + tid * 8;
    const __half* srcB = Wh + (size_t)nt * NTU * 2048 + tid * 8;

    float acc[4][8][4];
    #pragma unroll
    for (int mi = 0; mi < 4; mi++)
        #pragma unroll
        for (int ni = 0; ni < 8; ni++)
            #pragma unroll
            for (int q = 0; q < 4; q++) acc[mi][ni][q] = 0.f;

    auto fill = [&](int t2, int buf) {       // units 4*t2 .. 4*t2+3
        uint32_t d = base + (uint32_t)buf * M_STG_B + (uint32_t)tid * 16u;
        const __half* sa = srcA + (size_t)t2 * 8192;
        const __half* sb = srcB + (size_t)t2 * 8192;
        #pragma unroll
        for (int i = 0; i < 8; i++) {
            cp16(d + i * 2048u, sa + i * 1024);
            cp16(d + 16384u + i * 2048u, sb + i * 1024);
        }
    };
    auto domma = [&](int buf) {
        const uint32_t bo = (uint32_t)buf * M_STG_B;
        #pragma unroll
        for (int u = 0; u < 4; u++) {
            const uint32_t uo = bo + (uint32_t)u * 4096u;
            uint32_t a[4][4], b[4][4];
            #pragma unroll
            for (int mi = 0; mi < 4; mi++)
                ldsm4(a[mi], aAddr0 + uo + (uint32_t)mi * 512u);
            #pragma unroll
            for (int nj = 0; nj < 4; nj++)
                ldsm4(b[nj], bAddr0 + uo + (uint32_t)nj * 512u);
            #pragma unroll
            for (int mi = 0; mi < 4; mi++)
                #pragma unroll
                for (int ni = 0; ni < 8; ni++)
                    mma_f16(acc[mi][ni], a[mi][0], a[mi][1], a[mi][2], a[mi][3],
                            b[ni >> 1][(ni & 1) * 2], b[ni >> 1][(ni & 1) * 2 + 1]);
        }
    };

    fill(0, 0); CP_COMMIT();
    fill(1, 1); CP_COMMIT();
    for (int t2 = 0; t2 < NTM; t2++) {
        CP_WAIT1();                          // stage t2's group complete (own thread)
        __syncthreads();                     // all threads' stage-t2 data visible
        if (t2 + 2 < NTM) fill(t2 + 2, (t2 + 2) % STAGES_M);
        CP_COMMIT();
        domma(t2 % STAGES_M);
    }

    // epilogue: + bias, float2 stores
    const int nb = nt * 128, mb = mt * 128;
    #pragma unroll
    for (int ni = 0; ni < 8; ni++) {
        int col = nb + noff + ni * 8 + 2 * tig;
        float2 bb = *(const float2*)(bias + col);
        #pragma unroll
        for (int mi = 0; mi < 4; mi++) {
            int row0 = mb + moff + mi * 16 + gid;
            float2 v0 = { acc[mi][ni][0] + bb.x, acc[mi][ni][1] + bb.y };
            float2 v1 = { acc[mi][ni][2] + bb.x, acc[mi][ni][3] + bb.y };
            *(float2*)(out + (size_t)row0 * D_OUT + col)       = v0;
            *(float2*)(out + (size_t)(row0 + 8) * D_OUT + col) = v1;
        }
    }
}

// ============================================================================
extern "C" void kernel_launch(void* const* d_in, const int* in_sizes, int n_in,
                              void* d_out, int out_size)
{
    (void)in_sizes; (void)n_in; (void)out_size;
    const float* X     = (const float*)d_in[0];
    const float* W     = (const float*)d_in[1];
    const float* bias  = (const float*)d_in[2];
    const float* Acat  = (const float*)d_in[3];   // (N,R,D) flattens to (64,1280)
    const float* Bw    = (const float*)d_in[4];
    const float* scal  = (const float*)d_in[5];
    const float* masks = (const float*)d_in[6];
    float* out = (float*)d_out;

    cudaFuncSetAttribute(lora_g_kernel,
                         cudaFuncAttributeMaxDynamicSharedMemorySize, G_SMEM);
    cudaFuncSetAttribute(lora_main_kernel,
                         cudaFuncAttributeMaxDynamicSharedMemorySize, M_SMEM);

    convert_x_kernel<<<dim3(M_ROWS / 128, NTU_X), 128>>>(X);
    convert_w_kernel<<<dim3(D_OUT / 128, NTU), 128>>>(W, Bw);
    convert_a_kernel<<<NTU_X, 128>>>(Acat);
    lora_g_kernel<<<M_ROWS / 128, 128, G_SMEM>>>(scal, masks);
    lora_main_kernel<<<dim3(D_OUT / 128, M_ROWS / 128), 128, M_SMEM>>>(bias, out);
}

// round 13
// speedup vs baseline: 2.4633x; 1.0069x over previous
#include <cuda_runtime.h>
#include <cuda_fp16.h>
#include <cstdint>

#define DEVINL __device__ __forceinline__

// ---------------- problem dims ----------------
#define B_SZ   8
#define S_SZ   4096
#define D_IN   1280
#define D_OUT  1280
#define N_L    4
#define R_L    16
#define J_L    64                 /* N_L * R_L */
#define M_ROWS 32768              /* B_SZ * S_SZ */
#define K_TOT  1344               /* D_IN + J_L  */

// ---------------- tiling ----------------
#define KU      16                /* K per unit ktile */
#define NTU     (K_TOT / KU)      /* 84 unit ktiles */
#define NTU_X   (D_IN / KU)       /* 80 */
#define NTM     (NTU / 4)         /* 21 macro-stages (KC=64) in main kernel */
#define STAGES_M 3
#define STAGES_G 4

// Pre-swizzled fp16 operand tensors.
//   Xh[mtile][unit][2048 halves] (4KB tiles), Wh[ntile][unit][2048], Ah[unit][1024]
// 16B-chunk layout inside a tile (m = row, h = k>>3):
//   byte = (m>>2)*128 + (((m&3)*2 + (h ^ ((m>>2)&1))) * 16)
// Conflict-free for ldmatrix.x4 and identity cp.async; +16 rows => +512B (parity kept).
// 32-row-aligned sub-blocks are byte-contiguous (rows [r0,r0+32) -> bytes [r0*32, r0*32+1024)).
__device__ __half Xh[(size_t)(M_ROWS / 128) * NTU * 2048];
__device__ __half Wh[(size_t)(D_OUT / 128) * NTU * 2048];
__device__ __half Ah[(size_t)NTU_X * 1024];

// ---------------- helpers ----------------
DEVINL uint32_t cofs(int m, int h) {      // 16B-chunk byte offset within one tile
    int line = m >> 2;
    int slot = ((m & 3) * 2) + (h ^ (line & 1));
    return (uint32_t)(line * 128 + slot * 16);
}
DEVINL uint32_t pack2h(float a, float b) {
    __half2 h = __floats2half2_rn(a, b);
    return *reinterpret_cast<uint32_t*>(&h);
}
DEVINL void mma_f16(float c[4], uint32_t a0, uint32_t a1, uint32_t a2, uint32_t a3,
                    uint32_t b0, uint32_t b1) {
    asm volatile(
        "mma.sync.aligned.m16n8k16.row.col.f32.f16.f16.f32 "
        "{%0,%1,%2,%3}, {%4,%5,%6,%7}, {%8,%9}, {%0,%1,%2,%3};"
        : "+f"(c[0]), "+f"(c[1]), "+f"(c[2]), "+f"(c[3])
        : "r"(a0), "r"(a1), "r"(a2), "r"(a3), "r"(b0), "r"(b1));
}
DEVINL void ldsm4(uint32_t r[4], uint32_t addr) {
    asm volatile("ldmatrix.sync.aligned.m8n8.x4.shared.b16 {%0,%1,%2,%3}, [%4];"
                 : "=r"(r[0]), "=r"(r[1]), "=r"(r[2]), "=r"(r[3]) : "r"(addr));
}
DEVINL uint32_t smem_u32(const void* p) {
    uint32_t a;
    asm("{ .reg .u64 t; cvta.to.shared.u64 t, %1; cvt.u32.u64 %0, t; }" : "=r"(a) : "l"(p));
    return a;
}
DEVINL void cp16(uint32_t smem, const void* gptr) {
    asm volatile("cp.async.cg.shared.global [%0], [%1], 16;" :: "r"(smem), "l"(gptr) : "memory");
}
#define CP_COMMIT() asm volatile("cp.async.commit_group;" ::: "memory")
#define CP_WAIT1()  asm volatile("cp.async.wait_group 1;" ::: "memory")
#define CP_WAIT2()  asm volatile("cp.async.wait_group 2;" ::: "memory")

// ============================================================================
// Kernel 0a: Xh[mt][kt<80] = swizzled fp16(X)     grid (256, 80), 128 thr
// ============================================================================
__global__ void __launch_bounds__(128)
convert_x_kernel(const float* __restrict__ X)
{
    const int tid = threadIdx.x;
    const int mt = blockIdx.x, kt = blockIdx.y;
    char* dst = (char*)(Xh + ((size_t)mt * NTU + kt) * 2048);
    #pragma unroll
    for (int i = 0; i < 2; i++) {
        int idx = tid + i * 128;
        int m = idx >> 1, h = idx & 1;
        const float4* p = (const float4*)(X + (size_t)(mt * 128 + m) * D_IN + kt * KU + h * 8);
        float4 v0 = p[0], v1 = p[1];
        uint4 o = { pack2h(v0.x, v0.y), pack2h(v0.z, v0.w),
                    pack2h(v1.x, v1.y), pack2h(v1.z, v1.w) };
        *(uint4*)(dst + cofs(m, h)) = o;
    }
}

// ============================================================================
// Kernel 0b: Wh[nt][kt] from W (kt<80) / Bcat gather (kt>=80)   grid (10, 84)
//   Bcat[o][j] = Bw[j>>4][o][j&15]
// ============================================================================
__global__ void __launch_bounds__(128)
convert_w_kernel(const float* __restrict__ W, const float* __restrict__ Bw)
{
    const int tid = threadIdx.x;
    const int nt = blockIdx.x, kt = blockIdx.y;
    char* dst = (char*)(Wh + ((size_t)nt * NTU + kt) * 2048);
    #pragma unroll
    for (int i = 0; i < 2; i++) {
        int idx = tid + i * 128;
        int m = idx >> 1, h = idx & 1;
        const float4* p;
        if (kt < NTU_X) {
            p = (const float4*)(W + (size_t)(nt * 128 + m) * D_IN + kt * KU + h * 8);
        } else {
            p = (const float4*)(Bw + (size_t)(kt - NTU_X) * (D_OUT * R_L)
                                   + (size_t)(nt * 128 + m) * R_L + h * 8);
        }
        float4 v0 = p[0], v1 = p[1];
        uint4 o = { pack2h(v0.x, v0.y), pack2h(v0.z, v0.w),
                    pack2h(v1.x, v1.y), pack2h(v1.z, v1.w) };
        *(uint4*)(dst + cofs(m, h)) = o;
    }
}

// ============================================================================
// Kernel 0c: Ah[kt] = swizzled fp16(Acat)   (64 rows per tile)   grid (80)
// ============================================================================
__global__ void __launch_bounds__(128)
convert_a_kernel(const float* __restrict__ Acat)
{
    const int tid = threadIdx.x;
    const int kt = blockIdx.x;
    char* dst = (char*)(Ah + (size_t)kt * 1024);
    int m = tid >> 1, h = tid & 1;
    const float4* p = (const float4*)(Acat + (size_t)m * D_IN + kt * KU + h * 8);
    float4 v0 = p[0], v1 = p[1];
    uint4 o = { pack2h(v0.x, v0.y), pack2h(v0.z, v0.w),
                pack2h(v1.x, v1.y), pack2h(v1.z, v1.w) };
    *(uint4*)(dst + cofs(m, h)) = o;
}

// ============================================================================
// Kernel 1: LoRA activations -> Xh ktiles 80..83   [barrier-free, warp-private]
//   g[m][j] = scaling[j>>4]*mask[j>>4][m&4095] * (x[m].Acat[j]), fp16-rounded.
//   512 CTAs of 64 rows (one balanced wave at 4 CTAs/SM), 4 warps (2m x 2n),
//   warp tile 32x32.  Per warp per stage: A 1KB + B 1KB identity cp.async.
// ============================================================================
#define G_WB   2048                     /* bytes per warp per stage: A 1KB + B 1KB */
#define G_SB   (4 * G_WB)               /* 8192 per stage */
#define G_SMEM (STAGES_G * G_SB)        /* 32768 */
__global__ void __launch_bounds__(128, 4)
lora_g_kernel(const float* __restrict__ scalings, const float* __restrict__ masks)
{
    extern __shared__ char smc[];
    const int tid  = threadIdx.x;
    const int ht   = blockIdx.x & 1;      // which 64-row half of the 128-row tile
    const int mt   = blockIdx.x >> 1;
    const int lane = tid & 31;
    const int wid  = tid >> 5;
    const int gid  = lane >> 2, tig = lane & 3;
    const int moff = (wid & 1) * 32;      // local row offset within the 64-row half
    const int noff = (wid >> 1) * 32;
    const int r8   = lane & 7, g8 = lane >> 3;

    const uint32_t base  = smem_u32(smc);
    const uint32_t wbase = base + (uint32_t)wid * G_WB;
    const uint32_t aAddr0 = wbase + cofs(r8 + (g8 & 1) * 8, g8 >> 1);
    const uint32_t bAddr0 = wbase + 1024u + cofs(r8 + (g8 >> 1) * 8, g8 & 1);

    // 32-row-aligned blocks are contiguous: rows [r0,r0+32) -> bytes [r0*32,+1024)
    const __half* srcA = Xh + (size_t)mt * NTU * 2048 + (ht * 64 + moff) * 16 + lane * 8;
    const __half* srcB = Ah + noff * 16 + lane * 8;

    float acc[2][4][4];
    #pragma unroll
    for (int mi = 0; mi < 2; mi++)
        #pragma unroll
        for (int ni = 0; ni < 4; ni++)
            #pragma unroll
            for (int q = 0; q < 4; q++) acc[mi][ni][q] = 0.f;

    auto fill = [&](int t, int buf) {
        uint32_t d = wbase + (uint32_t)buf * G_SB + (uint32_t)lane * 16u;
        const __half* sa = srcA + (size_t)t * 2048;
        const __half* sb = srcB + (size_t)t * 1024;
        cp16(d,          sa);
        cp16(d + 512u,   sa + 256);
        cp16(d + 1024u,  sb);
        cp16(d + 1536u,  sb + 256);
    };
    auto domma = [&](int buf) {
        const uint32_t bo = (uint32_t)buf * G_SB;
        uint32_t a[2][4], b[2][4];
        #pragma unroll
        for (int mi = 0; mi < 2; mi++) ldsm4(a[mi], aAddr0 + bo + (uint32_t)mi * 512u);
        #pragma unroll
        for (int nj = 0; nj < 2; nj++) ldsm4(b[nj], bAddr0 + bo + (uint32_t)nj * 512u);
        #pragma unroll
        for (int mi = 0; mi < 2; mi++)
            #pragma unroll
            for (int ni = 0; ni < 4; ni++)
                mma_f16(acc[mi][ni], a[mi][0], a[mi][1], a[mi][2], a[mi][3],
                        b[ni >> 1][(ni & 1) * 2], b[ni >> 1][(ni & 1) * 2 + 1]);
    };

    #pragma unroll
    for (int t = 0; t < STAGES_G; t++) { fill(t, t); CP_COMMIT(); }
    for (int t = 0; t < NTU_X; t++) {
        CP_WAIT2();
        domma(t & 3);
        if (t + STAGES_G < NTU_X) fill(t + STAGES_G, t & 3);
        CP_COMMIT();
    }

    // epilogue: coef = scaling * mask, fp16-round, store into Xh ktiles 80..83
    float coef[2][2][2];
    #pragma unroll
    for (int mi = 0; mi < 2; mi++)
        #pragma unroll
        for (int h = 0; h < 2; h++) {
            int m = mt * 128 + ht * 64 + moff + mi * 16 + gid + h * 8;
            int s = m & (S_SZ - 1);
            #pragma unroll
            for (int sl = 0; sl < 2; sl++) {
                int subj = (noff >> 4) + sl;
                coef[mi][h][sl] = scalings[subj] * masks[subj * S_SZ + s];
            }
        }
    char* xblk = (char*)(Xh + (size_t)mt * NTU * 2048);
    #pragma unroll
    for (int mi = 0; mi < 2; mi++)
        #pragma unroll
        for (int ni = 0; ni < 4; ni++) {
            int col = noff + ni * 8 + 2 * tig;     // 0..63
            int sl  = (col >> 4) & 1;
            int kt  = NTU_X + (col >> 4);
            int kk  = col & 15;
            #pragma unroll
            for (int h = 0; h < 2; h++) {
                int rr = ht * 64 + moff + mi * 16 + gid + h * 8;   // row in 128-row tile
                uint32_t v = pack2h(acc[mi][ni][2 * h + 0] * coef[mi][h][sl],
                                    acc[mi][ni][2 * h + 1] * coef[mi][h][sl]);
                *(uint32_t*)(xblk + (size_t)kt * 4096 + cofs(rr, kk >> 3) + (kk & 7) * 2) = v;
            }
        }
}

// ============================================================================
// Kernel 2: out = [X|g] @ [W|Bcat]^T + bias   (K = 1344, fp16 MMA)
//   128 thr, 128x128 tile, 4 warps (2m x 2n), warp tile 64x64.
//   KC=64 macro-stages (21), 3-deep, 96KB smem, 2 CTAs/SM.
//   Fragment double-buffering: unit u+1's LDSM issued under unit u's HMMAs.
// ============================================================================
#define M_STG_B  32768                        /* bytes per macro-stage (A 16KB + B 16KB) */
#define M_SMEM   (STAGES_M * M_STG_B)         /* 98304 */
__global__ void __launch_bounds__(128, 2)
lora_main_kernel(const float* __restrict__ bias, float* __restrict__ out)
{
    extern __shared__ char smc[];
    const int tid  = threadIdx.x;
    const int nt   = blockIdx.x;          // x fastest: CTAs sharing mt hit Xh in L2
    const int mt   = blockIdx.y;
    const int lane = tid & 31;
    const int wid  = tid >> 5;
    const int gid  = lane >> 2, tig = lane & 3;
    const int moff = (wid & 1) * 64;
    const int noff = (wid >> 1) * 64;
    const int r8   = lane & 7, g8 = lane >> 3;

    const uint32_t base = smem_u32(smc);
    // stage layout: [A: 4 unit tiles, 16KB][B: 4 unit tiles, 16KB]
    const uint32_t aAddr0 = base + cofs(moff + r8 + (g8 & 1) * 8, g8 >> 1);
    const uint32_t bAddr0 = base + 16384u + cofs(noff + r8 + (g8 >> 1) * 8, g8 & 1);

    const __half* srcA = Xh + (size_t)mt * NTU * 2048 + tid * 8;
    const __half* srcB = Wh + (size_t)nt * NTU * 2048 + tid * 8;

    float acc[4][8][4];
    #pragma unroll
    for (int mi = 0; mi < 4; mi++)
        #pragma unroll
        for (int ni = 0; ni < 8; ni++)
            #pragma unroll
            for (int q = 0; q < 4; q++) acc[mi][ni][q] = 0.f;

    auto fill = [&](int t2, int buf) {       // units 4*t2 .. 4*t2+3
        uint32_t d = base + (uint32_t)buf * M_STG_B + (uint32_t)tid * 16u;
        const __half* sa = srcA + (size_t)t2 * 8192;
        const __half* sb = srcB + (size_t)t2 * 8192;
        #pragma unroll
        for (int i = 0; i < 8; i++) {
            cp16(d + i * 2048u, sa + i * 1024);
            cp16(d + 16384u + i * 2048u, sb + i * 1024);
        }
    };
    auto loadfrag = [&](uint32_t uo, uint32_t (*a)[4], uint32_t (*b)[4]) {
        #pragma unroll
        for (int mi = 0; mi < 4; mi++)
            ldsm4(a[mi], aAddr0 + uo + (uint32_t)mi * 512u);
        #pragma unroll
        for (int nj = 0; nj < 4; nj++)
            ldsm4(b[nj], bAddr0 + uo + (uint32_t)nj * 512u);
    };
    auto domma = [&](int buf) {
        const uint32_t bo = (uint32_t)buf * M_STG_B;
        uint32_t a[2][4][4], b[2][4][4];
        loadfrag(bo, a[0], b[0]);
        #pragma unroll
        for (int u = 0; u < 4; u++) {
            const int cur = u & 1;
            if (u < 3) loadfrag(bo + (uint32_t)(u + 1) * 4096u, a[cur ^ 1], b[cur ^ 1]);
            #pragma unroll
            for (int mi = 0; mi < 4; mi++)
                #pragma unroll
                for (int ni = 0; ni < 8; ni++)
                    mma_f16(acc[mi][ni],
                            a[cur][mi][0], a[cur][mi][1], a[cur][mi][2], a[cur][mi][3],
                            b[cur][ni >> 1][(ni & 1) * 2], b[cur][ni >> 1][(ni & 1) * 2 + 1]);
        }
    };

    fill(0, 0); CP_COMMIT();
    fill(1, 1); CP_COMMIT();
    for (int t2 = 0; t2 < NTM; t2++) {
        CP_WAIT1();                          // stage t2's group complete (own thread)
        __syncthreads();                     // all threads' stage-t2 data visible
        if (t2 + 2 < NTM) fill(t2 + 2, (t2 + 2) % STAGES_M);
        CP_COMMIT();
        domma(t2 % STAGES_M);
    }

    // epilogue: + bias, float2 stores
    const int nb = nt * 128, mb = mt * 128;
    #pragma unroll
    for (int ni = 0; ni < 8; ni++) {
        int col = nb + noff + ni * 8 + 2 * tig;
        float2 bb = *(const float2*)(bias + col);
        #pragma unroll
        for (int mi = 0; mi < 4; mi++) {
            int row0 = mb + moff + mi * 16 + gid;
            float2 v0 = { acc[mi][ni][0] + bb.x, acc[mi][ni][1] + bb.y };
            float2 v1 = { acc[mi][ni][2] + bb.x, acc[mi][ni][3] + bb.y };
            *(float2*)(out + (size_t)row0 * D_OUT + col)       = v0;
            *(float2*)(out + (size_t)(row0 + 8) * D_OUT + col) = v1;
        }
    }
}

// ============================================================================
extern "C" void kernel_launch(void* const* d_in, const int* in_sizes, int n_in,
                              void* d_out, int out_size)
{
    (void)in_sizes; (void)n_in; (void)out_size;
    const float* X     = (const float*)d_in[0];
    const float* W     = (const float*)d_in[1];
    const float* bias  = (const float*)d_in[2];
    const float* Acat  = (const float*)d_in[3];   // (N,R,D) flattens to (64,1280)
    const float* Bw    = (const float*)d_in[4];
    const float* scal  = (const float*)d_in[5];
    const float* masks = (const float*)d_in[6];
    float* out = (float*)d_out;

    cudaFuncSetAttribute(lora_g_kernel,
                         cudaFuncAttributeMaxDynamicSharedMemorySize, G_SMEM);
    cudaFuncSetAttribute(lora_main_kernel,
                         cudaFuncAttributeMaxDynamicSharedMemorySize, M_SMEM);

    convert_x_kernel<<<dim3(M_ROWS / 128, NTU_X), 128>>>(X);
    convert_w_kernel<<<dim3(D_OUT / 128, NTU), 128>>>(W, Bw);
    convert_a_kernel<<<NTU_X, 128>>>(Acat);
    lora_g_kernel<<<M_ROWS / 64, 128, G_SMEM>>>(scal, masks);
    lora_main_kernel<<<dim3(D_OUT / 128, M_ROWS / 128), 128, M_SMEM>>>(bias, out);
}